// round 9
// baseline (speedup 1.0000x reference)
#include <cuda_runtime.h>
#include <cuda_bf16.h>
#include <cstdint>

// ---------------------------------------------------------------------------
// Problem constants
// ---------------------------------------------------------------------------
constexpr int BATCH = 128;
constexpr int CCH   = 512;
constexpr int SS    = 1024;
constexpr int NPER  = CCH * SS;
constexpr float EPS = 1e-5f;

constexpr int KDIM   = 512;
constexpr int KC     = 64;            // K per chunk (128B row of bf16, SW128)
constexpr int NCHUNK = KDIM / KC;     // 8
constexpr int BM = 128, BN = 256;     // CTA tile
constexpr int THREADS = 512;          // 16 warps, each 32x64

// SMEM stage layout (bytes)
constexpr int ST_AHI = 0;                 // 128 rows x 128B
constexpr int ST_ALO = 16384;
constexpr int ST_BHI = 32768;             // 256 rows x 128B
constexpr int ST_BLO = 65536;
constexpr int STAGE_SZ = 98304;           // 96 KB
constexpr int SMEM_TOTAL = 2 * STAGE_SZ;  // 192 KB

#define SW128(o) ((o) ^ (((o) >> 3) & 0x70))

// ---------------------------------------------------------------------------
// Scratch
// ---------------------------------------------------------------------------
constexpr int NPART = 4;                        // ln_stats partials per sample
__device__ float g_ps[BATCH * NPART];
__device__ float g_pq[BATCH * NPART];
__device__ __nv_bfloat16 g_th[(size_t)BATCH * SS * CCH];
__device__ __nv_bfloat16 g_tl[(size_t)BATCH * SS * CCH];
__device__ __nv_bfloat16 g_hh[(size_t)BATCH * SS * CCH];
__device__ __nv_bfloat16 g_hl[(size_t)BATCH * SS * CCH];
__device__ __nv_bfloat16 g_w1h[CCH * CCH];
__device__ __nv_bfloat16 g_w1l[CCH * CCH];
__device__ __nv_bfloat16 g_w2h[CCH * CCH];
__device__ __nv_bfloat16 g_w2l[CCH * CCH];

// ---------------------------------------------------------------------------
// PTX wrappers (arch-neutral)
// ---------------------------------------------------------------------------
__device__ __forceinline__ uint32_t smem_u32(const void* p) {
    uint32_t a;
    asm("{ .reg .u64 t; cvta.to.shared.u64 t, %1; cvt.u32.u64 %0, t; }" : "=r"(a) : "l"(p));
    return a;
}
__device__ __forceinline__ void cp_async16(uint32_t saddr, const void* g) {
    asm volatile("cp.async.cg.shared.global [%0], [%1], 16;" :: "r"(saddr), "l"(g));
}
__device__ __forceinline__ void cp_commit() { asm volatile("cp.async.commit_group;"); }
template <int N>
__device__ __forceinline__ void cp_wait() { asm volatile("cp.async.wait_group %0;" :: "n"(N)); }

__device__ __forceinline__ void ldsm4(uint32_t& r0, uint32_t& r1, uint32_t& r2, uint32_t& r3,
                                      uint32_t addr) {
    asm volatile("ldmatrix.sync.aligned.m8n8.x4.shared.b16 {%0,%1,%2,%3}, [%4];"
                 : "=r"(r0), "=r"(r1), "=r"(r2), "=r"(r3) : "r"(addr));
}
__device__ __forceinline__ void mma_bf16(float* c, const uint32_t* a, const uint32_t* b) {
    asm volatile(
        "mma.sync.aligned.m16n8k16.row.col.f32.bf16.bf16.f32 "
        "{%0,%1,%2,%3}, {%4,%5,%6,%7}, {%8,%9}, {%0,%1,%2,%3};"
        : "+f"(c[0]), "+f"(c[1]), "+f"(c[2]), "+f"(c[3])
        : "r"(a[0]), "r"(a[1]), "r"(a[2]), "r"(a[3]), "r"(b[0]), "r"(b[1]));
}

// ---------------------------------------------------------------------------
// LN stats: 4 partial blocks per sample. grid=(NPART, BATCH), block=512.
// ---------------------------------------------------------------------------
__global__ void ln_stats_kernel(const float* __restrict__ x) {
    const int part = blockIdx.x;
    const int b    = blockIdx.y;
    const int n4p  = NPER / 4 / NPART;                    // 32768 float4 per part
    const float4* xb = reinterpret_cast<const float4*>(x + (size_t)b * NPER) + part * n4p;

    float s = 0.f, sq = 0.f;
    for (int i = threadIdx.x; i < n4p; i += blockDim.x) {
        float4 v = xb[i];
        s  += v.x + v.y + v.z + v.w;
        sq += v.x * v.x + v.y * v.y + v.z * v.z + v.w * v.w;
    }
    #pragma unroll
    for (int o = 16; o > 0; o >>= 1) {
        s  += __shfl_down_sync(0xffffffffu, s,  o);
        sq += __shfl_down_sync(0xffffffffu, sq, o);
    }
    __shared__ float shs[16], shq[16];
    const int wid = threadIdx.x >> 5, lane = threadIdx.x & 31;
    if (lane == 0) { shs[wid] = s; shq[wid] = sq; }
    __syncthreads();
    if (wid == 0) {
        const int nw = blockDim.x >> 5;
        s  = (lane < nw) ? shs[lane] : 0.f;
        sq = (lane < nw) ? shq[lane] : 0.f;
        #pragma unroll
        for (int o = 8; o > 0; o >>= 1) {
            s  += __shfl_down_sync(0xffffffffu, s,  o);
            sq += __shfl_down_sync(0xffffffffu, sq, o);
        }
        if (lane == 0) {
            g_ps[b * NPART + part] = s;
            g_pq[b * NPART + part] = sq;
        }
    }
}

// ---------------------------------------------------------------------------
// LN apply + transpose -> bf16 hi/lo tokens (B,S,C); bf16x2 stores.
// Finalizes mean/rstd from partials (deterministic 4-way sum).
// ---------------------------------------------------------------------------
__global__ void ln_apply_kernel(const float* __restrict__ x,
                                const float* __restrict__ lnw,
                                const float* __restrict__ lnb) {
    __shared__ float tile[32][65];      // [s][c], padded
    const int b  = blockIdx.z;
    const int c0 = blockIdx.y * 64;
    const int s0 = blockIdx.x * 32;
    const int tx = threadIdx.x, ty = threadIdx.y;

    const float sum  = (g_ps[b * NPART + 0] + g_ps[b * NPART + 1]) +
                       (g_ps[b * NPART + 2] + g_ps[b * NPART + 3]);
    const float sumq = (g_pq[b * NPART + 0] + g_pq[b * NPART + 1]) +
                       (g_pq[b * NPART + 2] + g_pq[b * NPART + 3]);
    const float mu   = sum / (float)NPER;
    const float rstd = rsqrtf(sumq / (float)NPER - mu * mu + EPS);

    #pragma unroll
    for (int r = 0; r < 8; r++) {
        const int cl = ty + r * 8;          // 0..63
        const int c  = c0 + cl;
        const int s  = s0 + tx;
        const size_t xi = ((size_t)b * CCH + c) * SS + s;
        const int    li = c * SS + s;
        tile[tx][cl] = (x[xi] - mu) * rstd * lnw[li] + lnb[li];
    }
    __syncthreads();
    #pragma unroll
    for (int r = 0; r < 4; r++) {
        const int sl = ty + r * 8;          // 0..31
        const float v0 = tile[sl][tx * 2 + 0];
        const float v1 = tile[sl][tx * 2 + 1];
        const __nv_bfloat16 h0 = __float2bfloat16_rn(v0);
        const __nv_bfloat16 h1 = __float2bfloat16_rn(v1);
        const __nv_bfloat16 l0 = __float2bfloat16_rn(v0 - __bfloat162float(h0));
        const __nv_bfloat16 l1 = __float2bfloat16_rn(v1 - __bfloat162float(h1));
        const size_t o = ((size_t)b * SS + (s0 + sl)) * CCH + c0 + tx * 2;
        *reinterpret_cast<__nv_bfloat162*>(g_th + o) = __nv_bfloat162(h0, h1);
        *reinterpret_cast<__nv_bfloat162*>(g_tl + o) = __nv_bfloat162(l0, l1);
    }
}

// ---------------------------------------------------------------------------
// fp32 -> bf16 hi/lo split (weights)
// ---------------------------------------------------------------------------
__global__ void split_kernel(const float* __restrict__ src,
                             __nv_bfloat16* __restrict__ hi,
                             __nv_bfloat16* __restrict__ lo, int n) {
    int i = blockIdx.x * blockDim.x + threadIdx.x;
    if (i < n) {
        float v = src[i];
        __nv_bfloat16 h = __float2bfloat16_rn(v);
        hi[i] = h;
        lo[i] = __float2bfloat16_rn(v - __bfloat162float(h));
    }
}

// ---------------------------------------------------------------------------
// Split-GEMM: CTA 128x256, 16 warps of 32x64, KC=64 double-buffered.
// ---------------------------------------------------------------------------
__device__ __forceinline__ void load_stage(
    const __nv_bfloat16* __restrict__ Ahi, const __nv_bfloat16* __restrict__ Alo,
    const __nv_bfloat16* __restrict__ Bhi, const __nv_bfloat16* __restrict__ Blo,
    int m0, int n0, int k0, uint32_t stage_u32, int tid)
{
    #pragma unroll
    for (int i = 0; i < 2; i++) {                 // A: 128 rows x 8 = 1024 vectors
        const int v = tid + i * THREADS, r = v >> 3, j = v & 7;
        cp_async16(stage_u32 + ST_AHI + SW128(r * 128 + j * 16),
                   Ahi + (size_t)(m0 + r) * KDIM + k0 + j * 8);
    }
    #pragma unroll
    for (int i = 0; i < 2; i++) {
        const int v = tid + i * THREADS, r = v >> 3, j = v & 7;
        cp_async16(stage_u32 + ST_ALO + SW128(r * 128 + j * 16),
                   Alo + (size_t)(m0 + r) * KDIM + k0 + j * 8);
    }
    #pragma unroll
    for (int i = 0; i < 4; i++) {                 // B: 256 rows x 8 = 2048 vectors
        const int v = tid + i * THREADS, r = v >> 3, j = v & 7;
        cp_async16(stage_u32 + ST_BHI + SW128(r * 128 + j * 16),
                   Bhi + (size_t)(n0 + r) * KDIM + k0 + j * 8);
    }
    #pragma unroll
    for (int i = 0; i < 4; i++) {
        const int v = tid + i * THREADS, r = v >> 3, j = v & 7;
        cp_async16(stage_u32 + ST_BLO + SW128(r * 128 + j * 16),
                   Blo + (size_t)(n0 + r) * KDIM + k0 + j * 8);
    }
}

template <bool GEMM1>
__global__ void __launch_bounds__(THREADS, 1)
gemm_mma(const __nv_bfloat16* __restrict__ Ahi, const __nv_bfloat16* __restrict__ Alo,
         const __nv_bfloat16* __restrict__ Bhi, const __nv_bfloat16* __restrict__ Blo,
         const float* __restrict__ bias,
         float* __restrict__ outF,
         __nv_bfloat16* __restrict__ outHi, __nv_bfloat16* __restrict__ outLo,
         size_t bZ, size_t outZ, int ldOut)
{
    extern __shared__ __align__(1024) char smem[];
    const uint32_t sbase = smem_u32(smem);
    const int tid  = threadIdx.x;
    const int w    = tid >> 5;
    const int lane = tid & 31;
    const int m0   = blockIdx.y * BM;
    const int n0   = blockIdx.x * BN;
    const size_t z = blockIdx.z;
    Bhi += z * bZ;
    Blo += z * bZ;

    const int warpM = (w & 3) * 32;     // 4 x 4 warp grid of 32x64 tiles
    const int warpN = (w >> 2) * 64;

    const int rA = (lane & 7) + ((lane >> 3) & 1) * 8;
    const int kA = (lane >> 4) * 16;
    const int rB = (lane & 7) + ((lane >> 4) & 1) * 8;
    const int kB = ((lane >> 3) & 1) * 16;

    float acc[2][8][4];                 // [mt 16-rows][n8][4]
    #pragma unroll
    for (int mt = 0; mt < 2; mt++)
        #pragma unroll
        for (int nt = 0; nt < 8; nt++)
            #pragma unroll
            for (int r = 0; r < 4; r++) acc[mt][nt][r] = 0.f;

    load_stage(Ahi, Alo, Bhi, Blo, m0, n0, 0, sbase, tid);
    cp_commit();

    for (int k = 0; k < NCHUNK; k++) {
        const uint32_t st = sbase + (k & 1) * STAGE_SZ;
        if (k + 1 < NCHUNK) {
            load_stage(Ahi, Alo, Bhi, Blo, m0, n0, (k + 1) * KC,
                       sbase + ((k + 1) & 1) * STAGE_SZ, tid);
            cp_commit();
            cp_wait<1>();
        } else {
            cp_wait<0>();
        }
        __syncthreads();

        #pragma unroll
        for (int ks = 0; ks < 4; ks++) {
            uint32_t ah[2][4], al[2][4];
            #pragma unroll
            for (int mt = 0; mt < 2; mt++) {
                const int off = SW128((warpM + mt * 16 + rA) * 128 + ks * 32 + kA);
                ldsm4(ah[mt][0], ah[mt][1], ah[mt][2], ah[mt][3], st + ST_AHI + off);
                ldsm4(al[mt][0], al[mt][1], al[mt][2], al[mt][3], st + ST_ALO + off);
            }
            #pragma unroll
            for (int np = 0; np < 4; np++) {        // 4 x 16-col groups
                uint32_t bh[4], bl[4];
                const int off = SW128((warpN + np * 16 + rB) * 128 + ks * 32 + kB);
                ldsm4(bh[0], bh[1], bh[2], bh[3], st + ST_BHI + off);
                ldsm4(bl[0], bl[1], bl[2], bl[3], st + ST_BLO + off);
                #pragma unroll
                for (int mt = 0; mt < 2; mt++)
                    #pragma unroll
                    for (int half = 0; half < 2; half++) {
                        float* a = acc[mt][np * 2 + half];
                        mma_bf16(a, ah[mt], &bh[half * 2]);   // hi*hi
                        mma_bf16(a, ah[mt], &bl[half * 2]);   // hi*lo
                        mma_bf16(a, al[mt], &bh[half * 2]);   // lo*hi
                    }
            }
        }
        __syncthreads();
    }

    // ---------------- epilogue ----------------
    const int g   = lane >> 2;
    const int c0l = (lane & 3) * 2;
    if (GEMM1) {
        #pragma unroll
        for (int mt = 0; mt < 2; mt++) {
            #pragma unroll
            for (int nt = 0; nt < 8; nt++) {
                const int col = n0 + warpN + nt * 8 + c0l;
                const float2 bv = *reinterpret_cast<const float2*>(bias + col);
                #pragma unroll
                for (int half = 0; half < 2; half++) {
                    const int row = m0 + warpM + mt * 16 + g + half * 8;
                    float v0 = fmaxf(acc[mt][nt][half * 2 + 0] + bv.x, 0.f);
                    float v1 = fmaxf(acc[mt][nt][half * 2 + 1] + bv.y, 0.f);
                    const __nv_bfloat16 h0 = __float2bfloat16_rn(v0);
                    const __nv_bfloat16 h1 = __float2bfloat16_rn(v1);
                    const __nv_bfloat16 l0 = __float2bfloat16_rn(v0 - __bfloat162float(h0));
                    const __nv_bfloat16 l1 = __float2bfloat16_rn(v1 - __bfloat162float(h1));
                    const size_t o = (size_t)row * ldOut + col;
                    *reinterpret_cast<__nv_bfloat162*>(outHi + o) = __nv_bfloat162(h0, h1);
                    *reinterpret_cast<__nv_bfloat162*>(outLo + o) = __nv_bfloat162(l0, l1);
                }
            }
        }
    } else {
        float* outZp = outF + z * outZ;
        #pragma unroll
        for (int mt = 0; mt < 2; mt++) {
            #pragma unroll
            for (int half = 0; half < 2; half++) {
                const int row = m0 + warpM + mt * 16 + g + half * 8;
                const float bm = bias[row];
                #pragma unroll
                for (int nt = 0; nt < 8; nt++) {
                    const int col = n0 + warpN + nt * 8 + c0l;
                    float2 v;
                    v.x = acc[mt][nt][half * 2 + 0] + bm;
                    v.y = acc[mt][nt][half * 2 + 1] + bm;
                    *reinterpret_cast<float2*>(outZp + (size_t)row * ldOut + col) = v;
                }
            }
        }
    }
}

// ---------------------------------------------------------------------------
extern "C" void kernel_launch(void* const* d_in, const int* in_sizes, int n_in,
                              void* d_out, int out_size) {
    const float* x   = (const float*)d_in[0];
    const float* lnw = (const float*)d_in[1];
    const float* lnb = (const float*)d_in[2];
    const float* w1  = (const float*)d_in[3];
    const float* b1  = (const float*)d_in[4];
    const float* w2  = (const float*)d_in[5];
    const float* b2  = (const float*)d_in[6];
    float* out = (float*)d_out;

    __nv_bfloat16 *th, *tl, *hh, *hl, *w1h, *w1l, *w2h, *w2l;
    cudaGetSymbolAddress((void**)&th,  g_th);
    cudaGetSymbolAddress((void**)&tl,  g_tl);
    cudaGetSymbolAddress((void**)&hh,  g_hh);
    cudaGetSymbolAddress((void**)&hl,  g_hl);
    cudaGetSymbolAddress((void**)&w1h, g_w1h);
    cudaGetSymbolAddress((void**)&w1l, g_w1l);
    cudaGetSymbolAddress((void**)&w2h, g_w2h);
    cudaGetSymbolAddress((void**)&w2l, g_w2l);

    cudaFuncSetAttribute(gemm_mma<true>,
                         cudaFuncAttributeMaxDynamicSharedMemorySize, SMEM_TOTAL);
    cudaFuncSetAttribute(gemm_mma<false>,
                         cudaFuncAttributeMaxDynamicSharedMemorySize, SMEM_TOTAL);

    split_kernel<<<(CCH * CCH + 255) / 256, 256>>>(w1, w1h, w1l, CCH * CCH);
    split_kernel<<<(CCH * CCH + 255) / 256, 256>>>(w2, w2h, w2l, CCH * CCH);

    ln_stats_kernel<<<dim3(NPART, BATCH), 512>>>(x);
    ln_apply_kernel<<<dim3(SS / 32, CCH / 64, BATCH), dim3(32, 8)>>>(x, lnw, lnb);

    // GEMM1: hdn[tok, d] = relu(t.w1^T + b1); M=131072, N=512, K=512
    gemm_mma<true><<<dim3(CCH / BN, (BATCH * SS) / BM, 1), THREADS, SMEM_TOTAL>>>(
        th, tl, w1h, w1l, b1, nullptr, hh, hl, 0, 0, CCH);

    // GEMM2 per sample: out_b[e, s] = w2[e,:].hdn_b[s,:] + b2[e]; M=512, N=1024
    gemm_mma<false><<<dim3(SS / BN, CCH / BM, BATCH), THREADS, SMEM_TOTAL>>>(
        w2h, w2l, hh, hl, b2, out, nullptr, nullptr,
        (size_t)SS * CCH, (size_t)CCH * SS, SS);
}

// round 10
// speedup vs baseline: 2.3547x; 2.3547x over previous
#include <cuda_runtime.h>
#include <cuda_fp16.h>
#include <cstdint>

// ---------------------------------------------------------------------------
// Problem constants
// ---------------------------------------------------------------------------
constexpr int BATCH = 128;
constexpr int CCH   = 512;
constexpr int SS    = 1024;
constexpr int NPER  = CCH * SS;
constexpr float EPS = 1e-5f;

constexpr int KDIM   = 512;
constexpr int KC     = 64;            // K per chunk (128B row of fp16, SW128)
constexpr int NCHUNK = KDIM / KC;     // 8
constexpr int BM = 128, BN = 128;     // CTA tile
constexpr int THREADS = 256;          // 8 warps of 32x64

// SMEM stage layout (bytes)
constexpr int ST_A = 0;                   // 128 rows x 128B = 16 KB
constexpr int ST_B = 16384;               // 128 rows x 128B = 16 KB
constexpr int STAGE_SZ = 32768;           // 32 KB
constexpr int SMEM_TOTAL = 2 * STAGE_SZ;  // 64 KB -> 2 CTAs/SM

#define SW128(o) ((o) ^ (((o) >> 3) & 0x70))

// ---------------------------------------------------------------------------
// Scratch
// ---------------------------------------------------------------------------
constexpr int NPART = 4;
__device__ float g_ps[BATCH * NPART];
__device__ float g_pq[BATCH * NPART];
__device__ __half g_t[(size_t)BATCH * SS * CCH];    // tokens fp16 (B,S,C)
__device__ __half g_hd[(size_t)BATCH * SS * CCH];   // hidden fp16 (B,S,C)
__device__ __half g_w1[CCH * CCH];
__device__ __half g_w2[CCH * CCH];

// ---------------------------------------------------------------------------
// PTX wrappers (arch-neutral)
// ---------------------------------------------------------------------------
__device__ __forceinline__ uint32_t smem_u32(const void* p) {
    uint32_t a;
    asm("{ .reg .u64 t; cvta.to.shared.u64 t, %1; cvt.u32.u64 %0, t; }" : "=r"(a) : "l"(p));
    return a;
}
__device__ __forceinline__ void cp_async16(uint32_t saddr, const void* g) {
    asm volatile("cp.async.cg.shared.global [%0], [%1], 16;" :: "r"(saddr), "l"(g));
}
__device__ __forceinline__ void cp_commit() { asm volatile("cp.async.commit_group;"); }
template <int N>
__device__ __forceinline__ void cp_wait() { asm volatile("cp.async.wait_group %0;" :: "n"(N)); }

__device__ __forceinline__ void ldsm4(uint32_t& r0, uint32_t& r1, uint32_t& r2, uint32_t& r3,
                                      uint32_t addr) {
    asm volatile("ldmatrix.sync.aligned.m8n8.x4.shared.b16 {%0,%1,%2,%3}, [%4];"
                 : "=r"(r0), "=r"(r1), "=r"(r2), "=r"(r3) : "r"(addr));
}
__device__ __forceinline__ void mma_f16(float* c, const uint32_t* a, const uint32_t* b) {
    asm volatile(
        "mma.sync.aligned.m16n8k16.row.col.f32.f16.f16.f32 "
        "{%0,%1,%2,%3}, {%4,%5,%6,%7}, {%8,%9}, {%0,%1,%2,%3};"
        : "+f"(c[0]), "+f"(c[1]), "+f"(c[2]), "+f"(c[3])
        : "r"(a[0]), "r"(a[1]), "r"(a[2]), "r"(a[3]), "r"(b[0]), "r"(b[1]));
}

// ---------------------------------------------------------------------------
// LN stats partials: grid=(NPART, BATCH), block=512.
// ---------------------------------------------------------------------------
__global__ void ln_stats_kernel(const float* __restrict__ x) {
    const int part = blockIdx.x;
    const int b    = blockIdx.y;
    const int n4p  = NPER / 4 / NPART;
    const float4* xb = reinterpret_cast<const float4*>(x + (size_t)b * NPER) + part * n4p;

    float s = 0.f, sq = 0.f;
    for (int i = threadIdx.x; i < n4p; i += blockDim.x) {
        float4 v = xb[i];
        s  += v.x + v.y + v.z + v.w;
        sq += v.x * v.x + v.y * v.y + v.z * v.z + v.w * v.w;
    }
    #pragma unroll
    for (int o = 16; o > 0; o >>= 1) {
        s  += __shfl_down_sync(0xffffffffu, s,  o);
        sq += __shfl_down_sync(0xffffffffu, sq, o);
    }
    __shared__ float shs[16], shq[16];
    const int wid = threadIdx.x >> 5, lane = threadIdx.x & 31;
    if (lane == 0) { shs[wid] = s; shq[wid] = sq; }
    __syncthreads();
    if (wid == 0) {
        const int nw = blockDim.x >> 5;
        s  = (lane < nw) ? shs[lane] : 0.f;
        sq = (lane < nw) ? shq[lane] : 0.f;
        #pragma unroll
        for (int o = 8; o > 0; o >>= 1) {
            s  += __shfl_down_sync(0xffffffffu, s,  o);
            sq += __shfl_down_sync(0xffffffffu, sq, o);
        }
        if (lane == 0) {
            g_ps[b * NPART + part] = s;
            g_pq[b * NPART + part] = sq;
        }
    }
}

// ---------------------------------------------------------------------------
// LN apply + transpose -> fp16 tokens (B,S,C); half2 stores.
// ---------------------------------------------------------------------------
__global__ void ln_apply_kernel(const float* __restrict__ x,
                                const float* __restrict__ lnw,
                                const float* __restrict__ lnb) {
    __shared__ float tile[32][65];      // [s][c], padded
    const int b  = blockIdx.z;
    const int c0 = blockIdx.y * 64;
    const int s0 = blockIdx.x * 32;
    const int tx = threadIdx.x, ty = threadIdx.y;

    const float sum  = (g_ps[b * NPART + 0] + g_ps[b * NPART + 1]) +
                       (g_ps[b * NPART + 2] + g_ps[b * NPART + 3]);
    const float sumq = (g_pq[b * NPART + 0] + g_pq[b * NPART + 1]) +
                       (g_pq[b * NPART + 2] + g_pq[b * NPART + 3]);
    const float mu   = sum / (float)NPER;
    const float rstd = rsqrtf(sumq / (float)NPER - mu * mu + EPS);

    #pragma unroll
    for (int r = 0; r < 8; r++) {
        const int cl = ty + r * 8;
        const int c  = c0 + cl;
        const int s  = s0 + tx;
        const size_t xi = ((size_t)b * CCH + c) * SS + s;
        const int    li = c * SS + s;
        tile[tx][cl] = (x[xi] - mu) * rstd * lnw[li] + lnb[li];
    }
    __syncthreads();
    #pragma unroll
    for (int r = 0; r < 4; r++) {
        const int sl = ty + r * 8;
        const float v0 = tile[sl][tx * 2 + 0];
        const float v1 = tile[sl][tx * 2 + 1];
        const size_t o = ((size_t)b * SS + (s0 + sl)) * CCH + c0 + tx * 2;
        *reinterpret_cast<__half2*>(g_t + o) = __floats2half2_rn(v0, v1);
    }
}

// ---------------------------------------------------------------------------
// fp32 -> fp16 weight convert
// ---------------------------------------------------------------------------
__global__ void convert_kernel(const float* __restrict__ src,
                               __half* __restrict__ dst, int n) {
    int i = blockIdx.x * blockDim.x + threadIdx.x;
    if (i < n * 2) { }
    if (i < n / 2) {
        float2 v = reinterpret_cast<const float2*>(src)[i];
        reinterpret_cast<__half2*>(dst)[i] = __floats2half2_rn(v.x, v.y);
    }
}

// ---------------------------------------------------------------------------
// fp16 GEMM via mma.sync: D[m,n] = sum_k A[m,k]*B[n,k].
// CTA 128x128, 8 warps of 32x64, KC=64 double-buffered, 2 CTAs/SM.
// ---------------------------------------------------------------------------
__device__ __forceinline__ void load_stage(
    const __half* __restrict__ A, const __half* __restrict__ B,
    int m0, int n0, int k0, uint32_t stage_u32, int tid)
{
    #pragma unroll
    for (int i = 0; i < 4; i++) {                 // A: 128 rows x 8 vec = 1024
        const int v = tid + i * THREADS, r = v >> 3, j = v & 7;
        cp_async16(stage_u32 + ST_A + SW128(r * 128 + j * 16),
                   A + (size_t)(m0 + r) * KDIM + k0 + j * 8);
    }
    #pragma unroll
    for (int i = 0; i < 4; i++) {                 // B: 128 rows x 8 vec = 1024
        const int v = tid + i * THREADS, r = v >> 3, j = v & 7;
        cp_async16(stage_u32 + ST_B + SW128(r * 128 + j * 16),
                   B + (size_t)(n0 + r) * KDIM + k0 + j * 8);
    }
}

template <bool GEMM1>   // GEMM1: col bias + relu + fp16 out. else: row bias + fp32 out.
__global__ void __launch_bounds__(THREADS, 2)
gemm_mma(const __half* __restrict__ A, const __half* __restrict__ B,
         const float* __restrict__ bias,
         float* __restrict__ outF, __half* __restrict__ outH,
         size_t bZ, size_t outZ, int ldOut)
{
    extern __shared__ __align__(1024) char smem[];
    const uint32_t sbase = smem_u32(smem);
    const int tid  = threadIdx.x;
    const int w    = tid >> 5;
    const int lane = tid & 31;
    const int m0   = blockIdx.y * BM;
    const int n0   = blockIdx.x * BN;
    const size_t z = blockIdx.z;
    B += z * bZ;

    const int warpM = (w & 3) * 32;     // 4 (m) x 2 (n) warp grid, warp tile 32x64
    const int warpN = (w >> 2) * 64;

    const int rA = (lane & 7) + ((lane >> 3) & 1) * 8;
    const int kA = (lane >> 4) * 16;
    const int rB = (lane & 7) + ((lane >> 4) & 1) * 8;
    const int kB = ((lane >> 3) & 1) * 16;

    float acc[2][8][4];                 // [m16][n8][4]
    #pragma unroll
    for (int mt = 0; mt < 2; mt++)
        #pragma unroll
        for (int nt = 0; nt < 8; nt++)
            #pragma unroll
            for (int r = 0; r < 4; r++) acc[mt][nt][r] = 0.f;

    load_stage(A, B, m0, n0, 0, sbase, tid);
    cp_commit();

    for (int k = 0; k < NCHUNK; k++) {
        const uint32_t st = sbase + (k & 1) * STAGE_SZ;
        if (k + 1 < NCHUNK) {
            load_stage(A, B, m0, n0, (k + 1) * KC, sbase + ((k + 1) & 1) * STAGE_SZ, tid);
            cp_commit();
            cp_wait<1>();
        } else {
            cp_wait<0>();
        }
        __syncthreads();

        #pragma unroll
        for (int ks = 0; ks < 4; ks++) {
            uint32_t a[2][4];
            #pragma unroll
            for (int mt = 0; mt < 2; mt++) {
                const int off = SW128((warpM + mt * 16 + rA) * 128 + ks * 32 + kA);
                ldsm4(a[mt][0], a[mt][1], a[mt][2], a[mt][3], st + ST_A + off);
            }
            #pragma unroll
            for (int np = 0; np < 4; np++) {
                uint32_t b[4];
                const int off = SW128((warpN + np * 16 + rB) * 128 + ks * 32 + kB);
                ldsm4(b[0], b[1], b[2], b[3], st + ST_B + off);
                #pragma unroll
                for (int mt = 0; mt < 2; mt++)
                    #pragma unroll
                    for (int half = 0; half < 2; half++)
                        mma_f16(acc[mt][np * 2 + half], a[mt], &b[half * 2]);
            }
        }
        __syncthreads();
    }

    // ---------------- epilogue ----------------
    const int g   = lane >> 2;
    const int c0l = (lane & 3) * 2;
    if (GEMM1) {
        #pragma unroll
        for (int mt = 0; mt < 2; mt++) {
            #pragma unroll
            for (int nt = 0; nt < 8; nt++) {
                const int col = n0 + warpN + nt * 8 + c0l;
                const float2 bv = *reinterpret_cast<const float2*>(bias + col);
                #pragma unroll
                for (int half = 0; half < 2; half++) {
                    const int row = m0 + warpM + mt * 16 + g + half * 8;
                    const float v0 = fmaxf(acc[mt][nt][half * 2 + 0] + bv.x, 0.f);
                    const float v1 = fmaxf(acc[mt][nt][half * 2 + 1] + bv.y, 0.f);
                    *reinterpret_cast<__half2*>(outH + (size_t)row * ldOut + col) =
                        __floats2half2_rn(v0, v1);
                }
            }
        }
    } else {
        float* outZp = outF + z * outZ;
        #pragma unroll
        for (int mt = 0; mt < 2; mt++) {
            #pragma unroll
            for (int half = 0; half < 2; half++) {
                const int row = m0 + warpM + mt * 16 + g + half * 8;
                const float bm = bias[row];
                #pragma unroll
                for (int nt = 0; nt < 8; nt++) {
                    const int col = n0 + warpN + nt * 8 + c0l;
                    float2 v;
                    v.x = acc[mt][nt][half * 2 + 0] + bm;
                    v.y = acc[mt][nt][half * 2 + 1] + bm;
                    *reinterpret_cast<float2*>(outZp + (size_t)row * ldOut + col) = v;
                }
            }
        }
    }
}

// ---------------------------------------------------------------------------
extern "C" void kernel_launch(void* const* d_in, const int* in_sizes, int n_in,
                              void* d_out, int out_size) {
    const float* x   = (const float*)d_in[0];
    const float* lnw = (const float*)d_in[1];
    const float* lnb = (const float*)d_in[2];
    const float* w1  = (const float*)d_in[3];
    const float* b1  = (const float*)d_in[4];
    const float* w2  = (const float*)d_in[5];
    const float* b2  = (const float*)d_in[6];
    float* out = (float*)d_out;

    __half *t, *hd, *w1h, *w2h;
    cudaGetSymbolAddress((void**)&t,   g_t);
    cudaGetSymbolAddress((void**)&hd,  g_hd);
    cudaGetSymbolAddress((void**)&w1h, g_w1);
    cudaGetSymbolAddress((void**)&w2h, g_w2);

    cudaFuncSetAttribute(gemm_mma<true>,
                         cudaFuncAttributeMaxDynamicSharedMemorySize, SMEM_TOTAL);
    cudaFuncSetAttribute(gemm_mma<false>,
                         cudaFuncAttributeMaxDynamicSharedMemorySize, SMEM_TOTAL);

    convert_kernel<<<(CCH * CCH / 2 + 255) / 256, 256>>>(w1, w1h, CCH * CCH);
    convert_kernel<<<(CCH * CCH / 2 + 255) / 256, 256>>>(w2, w2h, CCH * CCH);

    ln_stats_kernel<<<dim3(NPART, BATCH), 512>>>(x);
    ln_apply_kernel<<<dim3(SS / 32, CCH / 64, BATCH), dim3(32, 8)>>>(x, lnw, lnb);

    // GEMM1: hdn[tok, d] = relu(t.w1^T + b1); M=131072, N=512, K=512
    gemm_mma<true><<<dim3(CCH / BN, (BATCH * SS) / BM, 1), THREADS, SMEM_TOTAL>>>(
        t, w1h, b1, nullptr, hd, 0, 0, CCH);

    // GEMM2 per sample: out_b[e, s] = w2[e,:].hdn_b[s,:] + b2[e]; M=512, N=1024
    gemm_mma<false><<<dim3(SS / BN, CCH / BM, BATCH), THREADS, SMEM_TOTAL>>>(
        w2h, hd, b2, out, nullptr,
        (size_t)SS * CCH, (size_t)CCH * SS, SS);
}

// round 11
// speedup vs baseline: 2.4167x; 1.0263x over previous
#include <cuda_runtime.h>
#include <cuda_fp16.h>
#include <cstdint>

// ---------------------------------------------------------------------------
// Problem constants
// ---------------------------------------------------------------------------
constexpr int BATCH = 128;
constexpr int CCH   = 512;
constexpr int SS    = 1024;
constexpr int NPER  = CCH * SS;
constexpr float EPS = 1e-5f;

constexpr int KDIM   = 512;
constexpr int KC     = 64;            // K per chunk (128B row of fp16, SW128)
constexpr int NCHUNK = KDIM / KC;     // 8
constexpr int BM = 128, BN = 128;     // CTA tile
constexpr int THREADS = 128;          // 4 warps of 64x64
constexpr int NSTAGE = 3;

// SMEM stage layout (bytes)
constexpr int ST_A = 0;                        // 128 rows x 128B = 16 KB
constexpr int ST_B = 16384;                    // 128 rows x 128B = 16 KB
constexpr int STAGE_SZ = 32768;                // 32 KB
constexpr int SMEM_TOTAL = NSTAGE * STAGE_SZ;  // 96 KB -> 2 CTAs/SM

#define SW128(o) ((o) ^ (((o) >> 3) & 0x70))

// ---------------------------------------------------------------------------
// Scratch
// ---------------------------------------------------------------------------
constexpr int NPART = 4;
__device__ float g_ps[BATCH * NPART];
__device__ float g_pq[BATCH * NPART];
__device__ __half g_t[(size_t)BATCH * SS * CCH];    // tokens fp16 (B,S,C)
__device__ __half g_hd[(size_t)BATCH * SS * CCH];   // hidden fp16 (B,S,C)
__device__ __half g_w1[CCH * CCH];
__device__ __half g_w2[CCH * CCH];

// ---------------------------------------------------------------------------
// PTX wrappers (arch-neutral)
// ---------------------------------------------------------------------------
__device__ __forceinline__ uint32_t smem_u32(const void* p) {
    uint32_t a;
    asm("{ .reg .u64 t; cvta.to.shared.u64 t, %1; cvt.u32.u64 %0, t; }" : "=r"(a) : "l"(p));
    return a;
}
__device__ __forceinline__ void cp_async16(uint32_t saddr, const void* g) {
    asm volatile("cp.async.cg.shared.global [%0], [%1], 16;" :: "r"(saddr), "l"(g));
}
__device__ __forceinline__ void cp_commit() { asm volatile("cp.async.commit_group;"); }
template <int N>
__device__ __forceinline__ void cp_wait() { asm volatile("cp.async.wait_group %0;" :: "n"(N)); }

__device__ __forceinline__ void ldsm4(uint32_t& r0, uint32_t& r1, uint32_t& r2, uint32_t& r3,
                                      uint32_t addr) {
    asm volatile("ldmatrix.sync.aligned.m8n8.x4.shared.b16 {%0,%1,%2,%3}, [%4];"
                 : "=r"(r0), "=r"(r1), "=r"(r2), "=r"(r3) : "r"(addr));
}
__device__ __forceinline__ void mma_f16(float* c, const uint32_t* a, const uint32_t* b) {
    asm volatile(
        "mma.sync.aligned.m16n8k16.row.col.f32.f16.f16.f32 "
        "{%0,%1,%2,%3}, {%4,%5,%6,%7}, {%8,%9}, {%0,%1,%2,%3};"
        : "+f"(c[0]), "+f"(c[1]), "+f"(c[2]), "+f"(c[3])
        : "r"(a[0]), "r"(a[1]), "r"(a[2]), "r"(a[3]), "r"(b[0]), "r"(b[1]));
}

// ---------------------------------------------------------------------------
// LN stats partials: grid=(NPART, BATCH), block=512.
// ---------------------------------------------------------------------------
__global__ void ln_stats_kernel(const float* __restrict__ x) {
    const int part = blockIdx.x;
    const int b    = blockIdx.y;
    const int n4p  = NPER / 4 / NPART;
    const float4* xb = reinterpret_cast<const float4*>(x + (size_t)b * NPER) + part * n4p;

    float s = 0.f, sq = 0.f;
    for (int i = threadIdx.x; i < n4p; i += blockDim.x) {
        float4 v = xb[i];
        s  += v.x + v.y + v.z + v.w;
        sq += v.x * v.x + v.y * v.y + v.z * v.z + v.w * v.w;
    }
    #pragma unroll
    for (int o = 16; o > 0; o >>= 1) {
        s  += __shfl_down_sync(0xffffffffu, s,  o);
        sq += __shfl_down_sync(0xffffffffu, sq, o);
    }
    __shared__ float shs[16], shq[16];
    const int wid = threadIdx.x >> 5, lane = threadIdx.x & 31;
    if (lane == 0) { shs[wid] = s; shq[wid] = sq; }
    __syncthreads();
    if (wid == 0) {
        const int nw = blockDim.x >> 5;
        s  = (lane < nw) ? shs[lane] : 0.f;
        sq = (lane < nw) ? shq[lane] : 0.f;
        #pragma unroll
        for (int o = 8; o > 0; o >>= 1) {
            s  += __shfl_down_sync(0xffffffffu, s,  o);
            sq += __shfl_down_sync(0xffffffffu, sq, o);
        }
        if (lane == 0) {
            g_ps[b * NPART + part] = s;
            g_pq[b * NPART + part] = sq;
        }
    }
}

// ---------------------------------------------------------------------------
// LN apply + transpose -> fp16 tokens (B,S,C); half2 stores.
// ---------------------------------------------------------------------------
__global__ void ln_apply_kernel(const float* __restrict__ x,
                                const float* __restrict__ lnw,
                                const float* __restrict__ lnb) {
    __shared__ float tile[32][65];      // [s][c], padded
    const int b  = blockIdx.z;
    const int c0 = blockIdx.y * 64;
    const int s0 = blockIdx.x * 32;
    const int tx = threadIdx.x, ty = threadIdx.y;

    const float sum  = (g_ps[b * NPART + 0] + g_ps[b * NPART + 1]) +
                       (g_ps[b * NPART + 2] + g_ps[b * NPART + 3]);
    const float sumq = (g_pq[b * NPART + 0] + g_pq[b * NPART + 1]) +
                       (g_pq[b * NPART + 2] + g_pq[b * NPART + 3]);
    const float mu   = sum / (float)NPER;
    const float rstd = rsqrtf(sumq / (float)NPER - mu * mu + EPS);

    #pragma unroll
    for (int r = 0; r < 8; r++) {
        const int cl = ty + r * 8;
        const int c  = c0 + cl;
        const int s  = s0 + tx;
        const size_t xi = ((size_t)b * CCH + c) * SS + s;
        const int    li = c * SS + s;
        tile[tx][cl] = (x[xi] - mu) * rstd * lnw[li] + lnb[li];
    }
    __syncthreads();
    #pragma unroll
    for (int r = 0; r < 4; r++) {
        const int sl = ty + r * 8;
        const float v0 = tile[sl][tx * 2 + 0];
        const float v1 = tile[sl][tx * 2 + 1];
        const size_t o = ((size_t)b * SS + (s0 + sl)) * CCH + c0 + tx * 2;
        *reinterpret_cast<__half2*>(g_t + o) = __floats2half2_rn(v0, v1);
    }
}

// ---------------------------------------------------------------------------
// fp32 -> fp16 weight convert
// ---------------------------------------------------------------------------
__global__ void convert_kernel(const float* __restrict__ src,
                               __half* __restrict__ dst, int n) {
    int i = blockIdx.x * blockDim.x + threadIdx.x;
    if (i < n / 2) {
        float2 v = reinterpret_cast<const float2*>(src)[i];
        reinterpret_cast<__half2*>(dst)[i] = __floats2half2_rn(v.x, v.y);
    }
}

// ---------------------------------------------------------------------------
// fp16 GEMM via mma.sync: D[m,n] = sum_k A[m,k]*B[n,k].
// CTA 128x128, 4 warps of 64x64, KC=64, 3-stage pipeline, 2 CTAs/SM.
// ---------------------------------------------------------------------------
__device__ __forceinline__ void load_stage(
    const __half* __restrict__ A, const __half* __restrict__ B,
    int m0, int n0, int k0, uint32_t stage_u32, int tid)
{
    #pragma unroll
    for (int i = 0; i < 8; i++) {                 // A: 128 rows x 8 vec = 1024
        const int v = tid + i * THREADS, r = v >> 3, j = v & 7;
        cp_async16(stage_u32 + ST_A + SW128(r * 128 + j * 16),
                   A + (size_t)(m0 + r) * KDIM + k0 + j * 8);
    }
    #pragma unroll
    for (int i = 0; i < 8; i++) {                 // B: 128 rows x 8 vec = 1024
        const int v = tid + i * THREADS, r = v >> 3, j = v & 7;
        cp_async16(stage_u32 + ST_B + SW128(r * 128 + j * 16),
                   B + (size_t)(n0 + r) * KDIM + k0 + j * 8);
    }
}

template <bool GEMM1>   // GEMM1: col bias + relu + fp16 out. else: row bias + fp32 out.
__global__ void __launch_bounds__(THREADS, 2)
gemm_mma(const __half* __restrict__ A, const __half* __restrict__ B,
         const float* __restrict__ bias,
         float* __restrict__ outF, __half* __restrict__ outH,
         size_t bZ, size_t outZ, int ldOut)
{
    extern __shared__ __align__(1024) char smem[];
    const uint32_t sbase = smem_u32(smem);
    const int tid  = threadIdx.x;
    const int w    = tid >> 5;
    const int lane = tid & 31;
    const int m0   = blockIdx.y * BM;
    const int n0   = blockIdx.x * BN;
    const size_t z = blockIdx.z;
    B += z * bZ;

    const int warpM = (w & 1) * 64;     // 2 x 2 warp grid, warp tile 64x64
    const int warpN = (w >> 1) * 64;

    const int rA = (lane & 7) + ((lane >> 3) & 1) * 8;
    const int kA = (lane >> 4) * 16;
    const int rB = (lane & 7) + ((lane >> 4) & 1) * 8;
    const int kB = ((lane >> 3) & 1) * 16;

    float acc[4][8][4];                 // [m16][n8][4]
    #pragma unroll
    for (int mt = 0; mt < 4; mt++)
        #pragma unroll
        for (int nt = 0; nt < 8; nt++)
            #pragma unroll
            for (int r = 0; r < 4; r++) acc[mt][nt][r] = 0.f;

    load_stage(A, B, m0, n0, 0, sbase + 0 * STAGE_SZ, tid);
    cp_commit();
    load_stage(A, B, m0, n0, KC, sbase + 1 * STAGE_SZ, tid);
    cp_commit();

    int buf = 0;
    for (int k = 0; k < NCHUNK; k++) {
        if (k == NCHUNK - 1) { cp_wait<0>(); } else { cp_wait<1>(); }
        __syncthreads();
        if (k + 2 < NCHUNK) {
            int nb = buf + 2; if (nb >= NSTAGE) nb -= NSTAGE;
            load_stage(A, B, m0, n0, (k + 2) * KC, sbase + nb * STAGE_SZ, tid);
            cp_commit();
        }
        const uint32_t st = sbase + buf * STAGE_SZ;

        #pragma unroll
        for (int ks = 0; ks < 4; ks++) {
            uint32_t a[4][4];
            #pragma unroll
            for (int mt = 0; mt < 4; mt++) {
                const int off = SW128((warpM + mt * 16 + rA) * 128 + ks * 32 + kA);
                ldsm4(a[mt][0], a[mt][1], a[mt][2], a[mt][3], st + ST_A + off);
            }
            #pragma unroll
            for (int np = 0; np < 4; np++) {
                uint32_t b[4];
                const int off = SW128((warpN + np * 16 + rB) * 128 + ks * 32 + kB);
                ldsm4(b[0], b[1], b[2], b[3], st + ST_B + off);
                #pragma unroll
                for (int mt = 0; mt < 4; mt++)
                    #pragma unroll
                    for (int half = 0; half < 2; half++)
                        mma_f16(acc[mt][np * 2 + half], a[mt], &b[half * 2]);
            }
        }
        if (++buf == NSTAGE) buf = 0;
    }

    // ---------------- epilogue ----------------
    const int g   = lane >> 2;
    const int c0l = (lane & 3) * 2;
    if (GEMM1) {
        #pragma unroll
        for (int mt = 0; mt < 4; mt++) {
            #pragma unroll
            for (int nt = 0; nt < 8; nt++) {
                const int col = n0 + warpN + nt * 8 + c0l;
                const float2 bv = *reinterpret_cast<const float2*>(bias + col);
                #pragma unroll
                for (int half = 0; half < 2; half++) {
                    const int row = m0 + warpM + mt * 16 + g + half * 8;
                    const float v0 = fmaxf(acc[mt][nt][half * 2 + 0] + bv.x, 0.f);
                    const float v1 = fmaxf(acc[mt][nt][half * 2 + 1] + bv.y, 0.f);
                    *reinterpret_cast<__half2*>(outH + (size_t)row * ldOut + col) =
                        __floats2half2_rn(v0, v1);
                }
            }
        }
    } else {
        float* outZp = outF + z * outZ;
        #pragma unroll
        for (int mt = 0; mt < 4; mt++) {
            #pragma unroll
            for (int half = 0; half < 2; half++) {
                const int row = m0 + warpM + mt * 16 + g + half * 8;
                const float bm = bias[row];
                #pragma unroll
                for (int nt = 0; nt < 8; nt++) {
                    const int col = n0 + warpN + nt * 8 + c0l;
                    float2 v;
                    v.x = acc[mt][nt][half * 2 + 0] + bm;
                    v.y = acc[mt][nt][half * 2 + 1] + bm;
                    *reinterpret_cast<float2*>(outZp + (size_t)row * ldOut + col) = v;
                }
            }
        }
    }
}

// ---------------------------------------------------------------------------
extern "C" void kernel_launch(void* const* d_in, const int* in_sizes, int n_in,
                              void* d_out, int out_size) {
    const float* x   = (const float*)d_in[0];
    const float* lnw = (const float*)d_in[1];
    const float* lnb = (const float*)d_in[2];
    const float* w1  = (const float*)d_in[3];
    const float* b1  = (const float*)d_in[4];
    const float* w2  = (const float*)d_in[5];
    const float* b2  = (const float*)d_in[6];
    float* out = (float*)d_out;

    __half *t, *hd, *w1h, *w2h;
    cudaGetSymbolAddress((void**)&t,   g_t);
    cudaGetSymbolAddress((void**)&hd,  g_hd);
    cudaGetSymbolAddress((void**)&w1h, g_w1);
    cudaGetSymbolAddress((void**)&w2h, g_w2);

    cudaFuncSetAttribute(gemm_mma<true>,
                         cudaFuncAttributeMaxDynamicSharedMemorySize, SMEM_TOTAL);
    cudaFuncSetAttribute(gemm_mma<false>,
                         cudaFuncAttributeMaxDynamicSharedMemorySize, SMEM_TOTAL);

    convert_kernel<<<(CCH * CCH / 2 + 255) / 256, 256>>>(w1, w1h, CCH * CCH);
    convert_kernel<<<(CCH * CCH / 2 + 255) / 256, 256>>>(w2, w2h, CCH * CCH);

    ln_stats_kernel<<<dim3(NPART, BATCH), 512>>>(x);
    ln_apply_kernel<<<dim3(SS / 32, CCH / 64, BATCH), dim3(32, 8)>>>(x, lnw, lnb);

    // GEMM1: hdn[tok, d] = relu(t.w1^T + b1); M=131072, N=512, K=512
    gemm_mma<true><<<dim3(CCH / BN, (BATCH * SS) / BM, 1), THREADS, SMEM_TOTAL>>>(
        t, w1h, b1, nullptr, hd, 0, 0, CCH);

    // GEMM2 per sample: out_b[e, s] = w2[e,:].hdn_b[s,:] + b2[e]; M=512, N=1024
    gemm_mma<false><<<dim3(SS / BN, CCH / BM, BATCH), THREADS, SMEM_TOTAL>>>(
        w2h, hd, b2, out, nullptr,
        (size_t)SS * CCH, (size_t)CCH * SS, SS);
}

// round 12
// speedup vs baseline: 2.5555x; 1.0575x over previous
#include <cuda_runtime.h>
#include <cuda_fp16.h>
#include <cstdint>

// ---------------------------------------------------------------------------
// Problem constants
// ---------------------------------------------------------------------------
constexpr int BATCH = 128;
constexpr int CCH   = 512;
constexpr int SS    = 1024;
constexpr int NPER  = CCH * SS;
constexpr float EPS = 1e-5f;

constexpr int KDIM   = 512;
constexpr int KC     = 64;            // K per chunk
constexpr int NCHUNK = KDIM / KC;     // 8
constexpr int BM = 128, BN = 128;     // CTA tile
constexpr int THREADS = 128;          // 4 warps of 64x64
constexpr int NSTAGE = 3;

// SMEM stage layout (bytes)
constexpr int ST_A = 0;                        // 16 KB (either layout)
constexpr int ST_B = 16384;                    // 128 rows x 128B = 16 KB
constexpr int STAGE_SZ = 32768;                // 32 KB
constexpr int SMEM_TOTAL = NSTAGE * STAGE_SZ;  // 96 KB -> 2 CTAs/SM

#define SW128(o) ((o) ^ (((o) >> 3) & 0x70))

// ---------------------------------------------------------------------------
// Scratch
// ---------------------------------------------------------------------------
constexpr int NPART = 4;
__device__ float g_ps[BATCH * NPART];
__device__ float g_pq[BATCH * NPART];
__device__ __half g_t[(size_t)BATCH * CCH * SS];    // LN'd tokens, (B,C,S) layout
__device__ __half g_hd[(size_t)BATCH * SS * CCH];   // hidden fp16 (token-row-major)
__device__ __half g_w1[CCH * CCH];
__device__ __half g_w2[CCH * CCH];

// ---------------------------------------------------------------------------
// PTX wrappers (arch-neutral)
// ---------------------------------------------------------------------------
__device__ __forceinline__ uint32_t smem_u32(const void* p) {
    uint32_t a;
    asm("{ .reg .u64 t; cvta.to.shared.u64 t, %1; cvt.u32.u64 %0, t; }" : "=r"(a) : "l"(p));
    return a;
}
__device__ __forceinline__ void cp_async16(uint32_t saddr, const void* g) {
    asm volatile("cp.async.cg.shared.global [%0], [%1], 16;" :: "r"(saddr), "l"(g));
}
__device__ __forceinline__ void cp_commit() { asm volatile("cp.async.commit_group;"); }
template <int N>
__device__ __forceinline__ void cp_wait() { asm volatile("cp.async.wait_group %0;" :: "n"(N)); }

__device__ __forceinline__ void ldsm4(uint32_t& r0, uint32_t& r1, uint32_t& r2, uint32_t& r3,
                                      uint32_t addr) {
    asm volatile("ldmatrix.sync.aligned.m8n8.x4.shared.b16 {%0,%1,%2,%3}, [%4];"
                 : "=r"(r0), "=r"(r1), "=r"(r2), "=r"(r3) : "r"(addr));
}
__device__ __forceinline__ void ldsm4_t(uint32_t& r0, uint32_t& r1, uint32_t& r2, uint32_t& r3,
                                        uint32_t addr) {
    asm volatile("ldmatrix.sync.aligned.m8n8.x4.trans.shared.b16 {%0,%1,%2,%3}, [%4];"
                 : "=r"(r0), "=r"(r1), "=r"(r2), "=r"(r3) : "r"(addr));
}
__device__ __forceinline__ void mma_f16(float* c, const uint32_t* a, const uint32_t* b) {
    asm volatile(
        "mma.sync.aligned.m16n8k16.row.col.f32.f16.f16.f32 "
        "{%0,%1,%2,%3}, {%4,%5,%6,%7}, {%8,%9}, {%0,%1,%2,%3};"
        : "+f"(c[0]), "+f"(c[1]), "+f"(c[2]), "+f"(c[3])
        : "r"(a[0]), "r"(a[1]), "r"(a[2]), "r"(a[3]), "r"(b[0]), "r"(b[1]));
}

// ---------------------------------------------------------------------------
// LN stats partials: grid=(NPART, BATCH), block=512.
// ---------------------------------------------------------------------------
__global__ void ln_stats_kernel(const float* __restrict__ x) {
    const int part = blockIdx.x;
    const int b    = blockIdx.y;
    const int n4p  = NPER / 4 / NPART;
    const float4* xb = reinterpret_cast<const float4*>(x + (size_t)b * NPER) + part * n4p;

    float s = 0.f, sq = 0.f;
    for (int i = threadIdx.x; i < n4p; i += blockDim.x) {
        float4 v = xb[i];
        s  += v.x + v.y + v.z + v.w;
        sq += v.x * v.x + v.y * v.y + v.z * v.z + v.w * v.w;
    }
    #pragma unroll
    for (int o = 16; o > 0; o >>= 1) {
        s  += __shfl_down_sync(0xffffffffu, s,  o);
        sq += __shfl_down_sync(0xffffffffu, sq, o);
    }
    __shared__ float shs[16], shq[16];
    const int wid = threadIdx.x >> 5, lane = threadIdx.x & 31;
    if (lane == 0) { shs[wid] = s; shq[wid] = sq; }
    __syncthreads();
    if (wid == 0) {
        const int nw = blockDim.x >> 5;
        s  = (lane < nw) ? shs[lane] : 0.f;
        sq = (lane < nw) ? shq[lane] : 0.f;
        #pragma unroll
        for (int o = 8; o > 0; o >>= 1) {
            s  += __shfl_down_sync(0xffffffffu, s,  o);
            sq += __shfl_down_sync(0xffffffffu, sq, o);
        }
        if (lane == 0) {
            g_ps[b * NPART + part] = s;
            g_pq[b * NPART + part] = sq;
        }
    }
}

// ---------------------------------------------------------------------------
// LN apply, pure streaming: x (B,C,S) fp32 -> g_t (B,C,S) fp16.
// grid = (NPER/4/1024, BATCH), block 256, 4 float4 per thread.
// ---------------------------------------------------------------------------
__global__ void ln_apply_kernel(const float* __restrict__ x,
                                const float* __restrict__ lnw,
                                const float* __restrict__ lnb) {
    const int b = blockIdx.y;
    const float sum  = (g_ps[b * NPART + 0] + g_ps[b * NPART + 1]) +
                       (g_ps[b * NPART + 2] + g_ps[b * NPART + 3]);
    const float sumq = (g_pq[b * NPART + 0] + g_pq[b * NPART + 1]) +
                       (g_pq[b * NPART + 2] + g_pq[b * NPART + 3]);
    const float mu   = sum / (float)NPER;
    const float rstd = rsqrtf(sumq / (float)NPER - mu * mu + EPS);

    const float4* xb = reinterpret_cast<const float4*>(x + (size_t)b * NPER);
    const float4* wb = reinterpret_cast<const float4*>(lnw);
    const float4* bb = reinterpret_cast<const float4*>(lnb);
    uint2* tb = reinterpret_cast<uint2*>(g_t + (size_t)b * NPER);

    const int base = blockIdx.x * 1024 + threadIdx.x;
    #pragma unroll
    for (int it = 0; it < 4; it++) {
        const int i = base + it * 256;
        const float4 xv = xb[i];
        const float4 wv = wb[i];
        const float4 bv = bb[i];
        const float v0 = (xv.x - mu) * rstd * wv.x + bv.x;
        const float v1 = (xv.y - mu) * rstd * wv.y + bv.y;
        const float v2 = (xv.z - mu) * rstd * wv.z + bv.z;
        const float v3 = (xv.w - mu) * rstd * wv.w + bv.w;
        const __half2 h01 = __floats2half2_rn(v0, v1);
        const __half2 h23 = __floats2half2_rn(v2, v3);
        uint2 o;
        o.x = *reinterpret_cast<const uint32_t*>(&h01);
        o.y = *reinterpret_cast<const uint32_t*>(&h23);
        tb[i] = o;
    }
}

// ---------------------------------------------------------------------------
// fp32 -> fp16 weight convert
// ---------------------------------------------------------------------------
__global__ void convert_kernel(const float* __restrict__ src,
                               __half* __restrict__ dst, int n) {
    int i = blockIdx.x * blockDim.x + threadIdx.x;
    if (i < n / 2) {
        float2 v = reinterpret_cast<const float2*>(src)[i];
        reinterpret_cast<__half2*>(dst)[i] = __floats2half2_rn(v.x, v.y);
    }
}

// ---------------------------------------------------------------------------
// fp16 GEMM via mma.sync: D[m,n] = sum_k A[m,k]*B[n,k].
// TRANSA (GEMM1): A stored k-major (B,C,S); tile = 64 k-rows x 256B, XOR swizzle,
//                 fragments via ldmatrix.trans.
// else  (GEMM2): A row-major (w2), SW128 + ldmatrix.
// CTA 128x128, 4 warps of 64x64, KC=64, 3-stage pipeline, 2 CTAs/SM.
// ---------------------------------------------------------------------------
template <bool TRANSA>
__device__ __forceinline__ void load_stage(
    const __half* __restrict__ A, const __half* __restrict__ B,
    int m0, int n0, int k0, uint32_t stage_u32, int tid)
{
    if (TRANSA) {
        const int bz = m0 >> 10, s0 = m0 & 1023;
        const __half* Ab = A + ((size_t)bz * CCH) * SS + s0;
        #pragma unroll
        for (int i = 0; i < 8; i++) {             // 64 k-rows x 16 chunks of 16B
            const int v = tid + i * THREADS;
            const int r = v >> 4, j = v & 15;
            cp_async16(stage_u32 + ST_A + r * 256 + ((j ^ (r & 7)) * 16),
                       Ab + (size_t)(k0 + r) * SS + j * 8);
        }
    } else {
        #pragma unroll
        for (int i = 0; i < 8; i++) {             // 128 m-rows x 8 chunks
            const int v = tid + i * THREADS, r = v >> 3, j = v & 7;
            cp_async16(stage_u32 + ST_A + SW128(r * 128 + j * 16),
                       A + (size_t)(m0 + r) * KDIM + k0 + j * 8);
        }
    }
    #pragma unroll
    for (int i = 0; i < 8; i++) {                 // B: 128 rows x 8 chunks
        const int v = tid + i * THREADS, r = v >> 3, j = v & 7;
        cp_async16(stage_u32 + ST_B + SW128(r * 128 + j * 16),
                   B + (size_t)(n0 + r) * KDIM + k0 + j * 8);
    }
}

template <bool GEMM1>   // GEMM1: TRANSA + col bias + relu + fp16 out. else row bias + fp32 out.
__global__ void __launch_bounds__(THREADS, 2)
gemm_mma(const __half* __restrict__ A, const __half* __restrict__ B,
         const float* __restrict__ bias,
         float* __restrict__ outF, __half* __restrict__ outH,
         size_t bZ, size_t outZ, int ldOut)
{
    extern __shared__ __align__(1024) char smem[];
    const uint32_t sbase = smem_u32(smem);
    const int tid  = threadIdx.x;
    const int w    = tid >> 5;
    const int lane = tid & 31;
    const int m0   = blockIdx.y * BM;
    const int n0   = blockIdx.x * BN;
    const size_t z = blockIdx.z;
    B += z * bZ;

    const int warpM = (w & 1) * 64;     // 2 x 2 warp grid, warp tile 64x64
    const int warpN = (w >> 1) * 64;

    // non-trans A lane constants
    const int rA = (lane & 7) + ((lane >> 3) & 1) * 8;
    const int kA = (lane >> 4) * 16;
    // trans A lane constants: k-row within 16, m-half (0/1 -> +8 halfs = +16B chunk)
    const int krA = (lane & 7) + ((lane >> 4) & 1) * 8;
    const int mhA = (lane >> 3) & 1;
    // B lane constants
    const int rB = (lane & 7) + ((lane >> 4) & 1) * 8;
    const int kB = ((lane >> 3) & 1) * 16;

    float acc[4][8][4];                 // [m16][n8][4]
    #pragma unroll
    for (int mt = 0; mt < 4; mt++)
        #pragma unroll
        for (int nt = 0; nt < 8; nt++)
            #pragma unroll
            for (int r = 0; r < 4; r++) acc[mt][nt][r] = 0.f;

    load_stage<GEMM1>(A, B, m0, n0, 0, sbase + 0 * STAGE_SZ, tid);
    cp_commit();
    load_stage<GEMM1>(A, B, m0, n0, KC, sbase + 1 * STAGE_SZ, tid);
    cp_commit();

    int buf = 0;
    for (int k = 0; k < NCHUNK; k++) {
        if (k == NCHUNK - 1) { cp_wait<0>(); } else { cp_wait<1>(); }
        __syncthreads();
        if (k + 2 < NCHUNK) {
            int nb = buf + 2; if (nb >= NSTAGE) nb -= NSTAGE;
            load_stage<GEMM1>(A, B, m0, n0, (k + 2) * KC, sbase + nb * STAGE_SZ, tid);
            cp_commit();
        }
        const uint32_t st = sbase + buf * STAGE_SZ;

        #pragma unroll
        for (int ks = 0; ks < 4; ks++) {
            uint32_t a[4][4];
            #pragma unroll
            for (int mt = 0; mt < 4; mt++) {
                if (GEMM1) {
                    const int row   = ks * 16 + krA;
                    const int chunk = ((warpM + mt * 16) >> 3) + mhA;
                    const uint32_t addr =
                        st + ST_A + row * 256 + ((chunk ^ (row & 7)) * 16);
                    ldsm4_t(a[mt][0], a[mt][1], a[mt][2], a[mt][3], addr);
                } else {
                    const int off = SW128((warpM + mt * 16 + rA) * 128 + ks * 32 + kA);
                    ldsm4(a[mt][0], a[mt][1], a[mt][2], a[mt][3], st + ST_A + off);
                }
            }
            #pragma unroll
            for (int np = 0; np < 4; np++) {
                uint32_t b[4];
                const int off = SW128((warpN + np * 16 + rB) * 128 + ks * 32 + kB);
                ldsm4(b[0], b[1], b[2], b[3], st + ST_B + off);
                #pragma unroll
                for (int mt = 0; mt < 4; mt++)
                    #pragma unroll
                    for (int half = 0; half < 2; half++)
                        mma_f16(acc[mt][np * 2 + half], a[mt], &b[half * 2]);
            }
        }
        if (++buf == NSTAGE) buf = 0;
    }

    // ---------------- epilogue ----------------
    const int g   = lane >> 2;
    const int c0l = (lane & 3) * 2;
    if (GEMM1) {
        #pragma unroll
        for (int mt = 0; mt < 4; mt++) {
            #pragma unroll
            for (int nt = 0; nt < 8; nt++) {
                const int col = n0 + warpN + nt * 8 + c0l;
                const float2 bv = *reinterpret_cast<const float2*>(bias + col);
                #pragma unroll
                for (int half = 0; half < 2; half++) {
                    const int row = m0 + warpM + mt * 16 + g + half * 8;
                    const float v0 = fmaxf(acc[mt][nt][half * 2 + 0] + bv.x, 0.f);
                    const float v1 = fmaxf(acc[mt][nt][half * 2 + 1] + bv.y, 0.f);
                    *reinterpret_cast<__half2*>(outH + (size_t)row * ldOut + col) =
                        __floats2half2_rn(v0, v1);
                }
            }
        }
    } else {
        float* outZp = outF + z * outZ;
        #pragma unroll
        for (int mt = 0; mt < 4; mt++) {
            #pragma unroll
            for (int half = 0; half < 2; half++) {
                const int row = m0 + warpM + mt * 16 + g + half * 8;
                const float bm = bias[row];
                #pragma unroll
                for (int nt = 0; nt < 8; nt++) {
                    const int col = n0 + warpN + nt * 8 + c0l;
                    float2 v;
                    v.x = acc[mt][nt][half * 2 + 0] + bm;
                    v.y = acc[mt][nt][half * 2 + 1] + bm;
                    *reinterpret_cast<float2*>(outZp + (size_t)row * ldOut + col) = v;
                }
            }
        }
    }
}

// ---------------------------------------------------------------------------
extern "C" void kernel_launch(void* const* d_in, const int* in_sizes, int n_in,
                              void* d_out, int out_size) {
    const float* x   = (const float*)d_in[0];
    const float* lnw = (const float*)d_in[1];
    const float* lnb = (const float*)d_in[2];
    const float* w1  = (const float*)d_in[3];
    const float* b1  = (const float*)d_in[4];
    const float* w2  = (const float*)d_in[5];
    const float* b2  = (const float*)d_in[6];
    float* out = (float*)d_out;

    __half *t, *hd, *w1h, *w2h;
    cudaGetSymbolAddress((void**)&t,   g_t);
    cudaGetSymbolAddress((void**)&hd,  g_hd);
    cudaGetSymbolAddress((void**)&w1h, g_w1);
    cudaGetSymbolAddress((void**)&w2h, g_w2);

    cudaFuncSetAttribute(gemm_mma<true>,
                         cudaFuncAttributeMaxDynamicSharedMemorySize, SMEM_TOTAL);
    cudaFuncSetAttribute(gemm_mma<false>,
                         cudaFuncAttributeMaxDynamicSharedMemorySize, SMEM_TOTAL);

    convert_kernel<<<(CCH * CCH / 2 + 255) / 256, 256>>>(w1, w1h, CCH * CCH);
    convert_kernel<<<(CCH * CCH / 2 + 255) / 256, 256>>>(w2, w2h, CCH * CCH);

    ln_stats_kernel<<<dim3(NPART, BATCH), 512>>>(x);
    ln_apply_kernel<<<dim3(NPER / 4 / 1024, BATCH), 256>>>(x, lnw, lnb);

    // GEMM1: hdn[tok, d] = relu(t.w1^T + b1); A k-major via ldmatrix.trans.
    gemm_mma<true><<<dim3(CCH / BN, (BATCH * SS) / BM, 1), THREADS, SMEM_TOTAL>>>(
        t, w1h, b1, nullptr, hd, 0, 0, CCH);

    // GEMM2 per sample: out_b[e, s] = w2[e,:].hdn_b[s,:] + b2[e]
    gemm_mma<false><<<dim3(SS / BN, CCH / BM, BATCH), THREADS, SMEM_TOTAL>>>(
        w2h, hd, b2, out, nullptr,
        (size_t)SS * CCH, (size_t)CCH * SS, SS);
}